// round 16
// baseline (speedup 1.0000x reference)
#include <cuda_runtime.h>
#include <cuda_fp16.h>
#include <math.h>
#include <stdint.h>

#define Bv 16384
#define Dv 256
#define Ev 8
#define NBv 17          // blocks per expert -> 136 blocks, one wave
#define MT 256          // tokens per tile (ONE tile per block)
#define TPB 512

__device__ int   g_count[Ev];        // zero at load; re-zeroed by k_expert
__device__ int   g_tok[Ev][Bv];
__device__ float g_w[Ev][Bv];
// fp16 hi images: W1 [e][quarter(4)] 16KB each (512KB), Wp [e] 32KB (256KB)
__device__ uint4 g_img4[1572864 / 16];
// fp16 image of feat: [16384 tokens][256 fp16] = 8MB (32 uint4/token)
__device__ uint4 g_f16[16384 * 32];

__device__ __forceinline__ uint32_t smem_u32(const void* p) {
    uint32_t a;
    asm("{ .reg .u64 t; cvta.to.shared.u64 t, %1; cvt.u32.u64 %0, t; }"
        : "=r"(a) : "l"(p));
    return a;
}
__device__ __forceinline__ uint32_t packhf(float even, float odd) {
    uint32_t r;
    asm("cvt.rn.f16x2.f32 %0, %1, %2;" : "=r"(r) : "f"(odd), "f"(even));
    return r;
}
__device__ __forceinline__ void ldsm4(uint32_t addr, uint32_t* r) {
    asm volatile("ldmatrix.sync.aligned.m8n8.x4.shared.b16 {%0,%1,%2,%3}, [%4];"
        : "=r"(r[0]), "=r"(r[1]), "=r"(r[2]), "=r"(r[3]) : "r"(addr));
}
__device__ __forceinline__ void mma_hf(float* d, const uint32_t* a,
                                       uint32_t b0, uint32_t b1) {
    asm volatile("mma.sync.aligned.m16n8k16.row.col.f32.f16.f16.f32 "
        "{%0,%1,%2,%3}, {%4,%5,%6,%7}, {%8,%9}, {%0,%1,%2,%3};"
        : "+f"(d[0]), "+f"(d[1]), "+f"(d[2]), "+f"(d[3])
        : "r"(a[0]), "r"(a[1]), "r"(a[2]), "r"(a[3]), "r"(b0), "r"(b1));
}

// ---- k_front: gate (blocks 0..255) + weight-image prep (blocks 256..383) ----
__global__ void __launch_bounds__(256) k_front(const float* __restrict__ feat,
                                               const float* __restrict__ Wg,
                                               const float* __restrict__ W1,
                                               const float* __restrict__ Wp,
                                               float* __restrict__ out) {
    const int tid = threadIdx.x;
    unsigned char* img = (unsigned char*)g_img4;

    if (blockIdx.x >= 256) {
        // ---------------- prep part ----------------
        const int idx = blockIdx.x - 256;
        const int e = idx >> 4;
        const int p = idx & 15;
        for (int qq = 0; qq < 4; qq++) {
            int i = (p * 4 + qq) * 256 + tid;
            int h = i >> 7, d2 = i & 127;
            int dg = d2 * 2;
            float v0 = W1[e * 32768 + dg * 128 + h];
            float v1 = W1[e * 32768 + (dg + 1) * 128 + h];
            int quarter = dg >> 6, dl = dg & 63;
            uint32_t off = (uint32_t)h * 128
                         + (((uint32_t)dl * 2) ^ ((h & 7) * 16));
            *(uint32_t*)(img + (uint32_t)(e * 4 + quarter) * 16384u + off)
                = packhf(v0, v1);
        }
        for (int qq = 0; qq < 2; qq++) {
            int i = (p * 2 + qq) * 256 + tid;
            int k = i >> 6, h2 = i & 63;
            int hg = h2 * 2;
            float v0 = Wp[e * 16384 + hg * 128 + k];
            float v1 = Wp[e * 16384 + (hg + 1) * 128 + k];
            uint32_t off = (uint32_t)k * 256
                         + (((uint32_t)hg * 2) ^ ((k & 7) * 16));
            *(uint32_t*)(img + 524288u + (uint32_t)e * 32768u + off)
                = packhf(v0, v1);
        }
        return;
    }

    // ---------------- gate part ----------------
    __shared__ float WgT[Ev * 256];
    __shared__ float w0s[64], w1s[64];
    __shared__ int   e0s[64], e1s[64];
    __shared__ int   cnt[Ev], gbase[Ev], cur[Ev];

    for (int i = tid; i < Dv * Ev; i += 256)
        WgT[(i & 7) * 256 + (i >> 3)] = Wg[i];
    if (tid < Ev) cnt[tid] = 0;
    __syncthreads();

    const int tq  = tid & 3;           // quad lane -> d range [tq*64, tq*64+64)
    const int tl  = tid >> 2;          // local token 0..63
    const int tok = blockIdx.x * 64 + tl;
    const float* x = feat + (size_t)tok * Dv + tq * 64;
    unsigned char* f16 = (unsigned char*)g_f16;

    float acc[Ev];
#pragma unroll
    for (int e = 0; e < Ev; e++) acc[e] = 0.f;
#pragma unroll
    for (int i = 0; i < 16; i++) {
        float4 x4 = *(const float4*)(x + i * 4);
        *(uint2*)(f16 + (size_t)tok * 512 + tq * 128 + i * 8) =
            make_uint2(packhf(x4.x, x4.y), packhf(x4.z, x4.w));
#pragma unroll
        for (int e = 0; e < Ev; e++) {
            const float* wr = WgT + e * 256 + tq * 64 + i * 4;
            acc[e] += x4.x * wr[0] + x4.y * wr[1] + x4.z * wr[2] + x4.w * wr[3];
        }
    }
#pragma unroll
    for (int e = 0; e < Ev; e++) {
        acc[e] += __shfl_xor_sync(0xffffffffu, acc[e], 1);
        acc[e] += __shfl_xor_sync(0xffffffffu, acc[e], 2);
    }

    if (tq == 0) {
        out[tok] = 0.f;
        float m = acc[0];
#pragma unroll
        for (int e = 1; e < Ev; e++) m = fmaxf(m, acc[e]);
        float g[Ev], sum = 0.f;
#pragma unroll
        for (int e = 0; e < Ev; e++) { g[e] = expf(acc[e] - m); sum += g[e]; }
        float inv = 1.f / sum;
#pragma unroll
        for (int e = 0; e < Ev; e++) g[e] *= inv;
        int i0 = 0;
#pragma unroll
        for (int e = 1; e < Ev; e++) if (g[e] > g[i0]) i0 = e;
        int i1 = -1;
#pragma unroll
        for (int e = 0; e < Ev; e++) {
            if (e == i0) continue;
            if (i1 < 0 || g[e] > g[i1]) i1 = e;
        }
        float denom = g[i0] + g[i1] + 1e-10f;
        e0s[tl] = i0; w0s[tl] = g[i0] / denom;
        e1s[tl] = i1; w1s[tl] = g[i1] / denom;
    }
    __syncthreads();

    if (tid < 64) {
        atomicAdd(&cnt[e0s[tid]], 1);
        atomicAdd(&cnt[e1s[tid]], 1);
    }
    __syncthreads();
    if (tid < Ev) {
        gbase[tid] = atomicAdd(&g_count[tid], cnt[tid]);
        cur[tid] = 0;
    }
    __syncthreads();
    if (tid < 64) {
        int t2 = blockIdx.x * 64 + tid;
        int e0 = e0s[tid];
        int p0 = atomicAdd(&cur[e0], 1);
        g_tok[e0][gbase[e0] + p0] = t2;
        g_w[e0][gbase[e0] + p0] = w0s[tid];
        int e1 = e1s[tid];
        int p1 = atomicAdd(&cur[e1], 1);
        g_tok[e1][gbase[e1] + p1] = t2;
        g_w[e1][gbase[e1] + p1] = w1s[tid];
    }
}

// smem map (bytes):
//   BUF 0..65536: GEMM1: A_hi 0 (32K), W1q 32768 (16K)
//                 GEMM2: core_hi 0..65536 (256 rows x 256B)
//   Wp 65536 (32K), tk 98304 (1K), wt 99328 (1K),
//   b1 100352, bp 100864, Wo 101376 -> 101888
#define OFF_WH  32768
#define OFF_PH  65536
#define SMEM_BYTES 101888

__global__ void __launch_bounds__(TPB, 1) k_expert(
    const float* __restrict__ b1g, const float* __restrict__ bpg,
    const float* __restrict__ mix_logit,
    const float* __restrict__ Wog, const float* __restrict__ bog,
    float* __restrict__ out)
{
    extern __shared__ __align__(1024) char smb[];
    int*   tk   = (int*)(smb + 98304);
    float* wt   = (float*)(smb + 99328);
    float* b1_s = (float*)(smb + 100352);
    float* bp_s = (float*)(smb + 100864);
    float* Wo_s = (float*)(smb + 101376);

    const int e    = blockIdx.x & 7;
    const int j    = blockIdx.x >> 3;
    const int tid  = threadIdx.x;
    const int warp = tid >> 5;
    const int lane = tid & 31;
    const int mw   = warp & 7;     // M group: 32 tokens (two 16-row strips)
    const int nh   = warp >> 3;    // N half: 64 cols
    const int li   = lane & 3;
    const int lg   = lane >> 2;
    const uint32_t sb = smem_u32(smb);
    const unsigned char* f16 = (const unsigned char*)g_f16;

    {
        const uint4* s = g_img4 + 32768 + (size_t)e * 2048;
        uint4* d = (uint4*)(smb + OFF_PH);
        for (int u = tid; u < 2048; u += TPB) d[u] = s[u];
    }
    if (tid < 128) {
        b1_s[tid] = b1g[e * 128 + tid];
        bp_s[tid] = bpg[e * 128 + tid];
        Wo_s[tid] = Wog[e * 128 + tid];
    }
    const float mix  = 1.f / (1.f + expf(-mix_logit[e]));
    const float omix = 1.f - mix;
    const float boe  = (nh == 0) ? bog[e] : 0.f;
    const int   n    = g_count[e];   // read at block start (wave-1 co-resident)

    const int matA = lane >> 3;
    const uint32_t a_koff = (uint32_t)(matA >> 1) * 16;
    const uint32_t sw     = (uint32_t)(lane & 7) * 16;
    const uint32_t arow0  = (uint32_t)(mw * 32 + (matA & 1) * 8 + (lane & 7));
    const int jt = matA >> 1, kc = matA & 1;
    const uint32_t brow0  = (uint32_t)(nh * 64 + jt * 8 + (lane & 7)); // +ntp*16
    const uint32_t b_koff = (uint32_t)kc * 16;

    for (int tile = j; tile * MT < n; tile += NBv) {
        const int base = tile * MT;
        __syncthreads();               // Wp staged / prev-tile reads done
        if (tid < 256) {
            int idx = min(base + tid, n - 1);
            tk[tid] = g_tok[e][idx];
            wt[tid] = g_w[e][idx];
        }

        float D1[2][8][4];
#pragma unroll
        for (int s = 0; s < 2; s++)
#pragma unroll
            for (int t = 0; t < 8; t++)
#pragma unroll
                for (int q = 0; q < 4; q++) D1[s][t][q] = 0.f;

        // ===== GEMM1 over 4 K-quarters: D1 = Ah @ W1h =====
        for (int q = 0; q < 4; q++) {
            __syncthreads();           // tk ready / prev quarter reads done
            for (int u = tid; u < 2048; u += TPB) {    // A quarter copy (fp16)
                int ts = u >> 3, c = u & 7;
                uint4 v = *(const uint4*)(f16 + (size_t)tk[ts] * 512
                                          + q * 128 + c * 16);
                uint32_t off = (uint32_t)ts * 128
                             + (((uint32_t)c * 16) ^ ((ts & 7) * 16));
                *(uint4*)(smb + off) = v;
            }
            {   // W1 quarter image (pre-swizzled fp16, 128B rows)
                const uint4* s = g_img4 + (size_t)(e * 4 + q) * 1024;
                uint4* d = (uint4*)(smb + OFF_WH);
                for (int u = tid; u < 1024; u += TPB) d[u] = s[u];
            }
            __syncthreads();

            for (int ks = 0; ks < 4; ks++) {
                uint32_t kx  = (uint32_t)ks * 32;
                uint32_t akx = (kx + a_koff) ^ sw;
                uint32_t ah0[4], ah1[4];
                ldsm4(sb + arow0 * 128 + akx, ah0);
                ldsm4(sb + (arow0 + 16) * 128 + akx, ah1);
#pragma unroll
                for (int ntp = 0; ntp < 4; ntp++) {
                    uint32_t bkx = ((kx + b_koff) ^ sw)
                                 + (brow0 + ntp * 16) * 128;
                    uint32_t bh[4];
                    ldsm4(sb + OFF_WH + bkx, bh);
                    mma_hf(D1[0][2 * ntp],     ah0, bh[0], bh[1]);
                    mma_hf(D1[0][2 * ntp + 1], ah0, bh[2], bh[3]);
                    mma_hf(D1[1][2 * ntp],     ah1, bh[0], bh[1]);
                    mma_hf(D1[1][2 * ntp + 1], ah1, bh[2], bh[3]);
                }
            }
        }

        // ===== epilogue 1: relu+b1; Wo partial; core(hi fp16) -> smem =====
        __syncthreads();               // GEMM1 reads done -> BUF becomes core
        float s1[2][2];
#pragma unroll
        for (int s = 0; s < 2; s++) {
            const int tok0 = mw * 32 + s * 16 + lg;
            const uint32_t sw0 = (uint32_t)(tok0 & 7) * 16;
            const uint32_t sw1 = (uint32_t)((tok0 + 8) & 7) * 16;
            float a = 0.f, b = 0.f;
#pragma unroll
            for (int t = 0; t < 8; t++) {
                int h0 = nh * 64 + (t >> 1) * 16 + (t & 1) * 8 + li * 2;
                float2 b1v = *(float2*)(b1_s + h0);
                float2 wov = *(float2*)(Wo_s + h0);
                float c0 = fmaxf(D1[s][t][0] + b1v.x, 0.f);
                float c1 = fmaxf(D1[s][t][1] + b1v.y, 0.f);
                float c2 = fmaxf(D1[s][t][2] + b1v.x, 0.f);
                float c3 = fmaxf(D1[s][t][3] + b1v.y, 0.f);
                a += c0 * wov.x + c1 * wov.y;
                b += c2 * wov.x + c3 * wov.y;
                uint32_t col = (uint32_t)h0 * 2;
                uint32_t o0 = (uint32_t)tok0 * 256 + (col ^ sw0);
                uint32_t o1 = (uint32_t)(tok0 + 8) * 256 + (col ^ sw1);
                *(uint32_t*)(smb + o0) = packhf(c0, c1);
                *(uint32_t*)(smb + o1) = packhf(c2, c3);
            }
            s1[s][0] = a; s1[s][1] = b;
        }
        __syncthreads();

        // ===== GEMM2: D2 = core_h @ Wp_h =====
        float D2[2][8][4];
#pragma unroll
        for (int s = 0; s < 2; s++)
#pragma unroll
            for (int t = 0; t < 8; t++)
#pragma unroll
                for (int q = 0; q < 4; q++) D2[s][t][q] = 0.f;
        for (int ks = 0; ks < 8; ks++) {
            uint32_t kx  = (uint32_t)ks * 32;
            uint32_t akx = (kx + a_koff) ^ sw;
            uint32_t ah0[4], ah1[4];
            ldsm4(sb + arow0 * 256 + akx, ah0);
            ldsm4(sb + (arow0 + 16) * 256 + akx, ah1);
#pragma unroll
            for (int ntp = 0; ntp < 4; ntp++) {
                uint32_t bkx = ((kx + b_koff) ^ sw) + (brow0 + ntp * 16) * 256;
                uint32_t bh[4];
                ldsm4(sb + OFF_PH + bkx, bh);
                mma_hf(D2[0][2 * ntp],     ah0, bh[0], bh[1]);
                mma_hf(D2[0][2 * ntp + 1], ah0, bh[2], bh[3]);
                mma_hf(D2[1][2 * ntp],     ah1, bh[0], bh[1]);
                mma_hf(D2[1][2 * ntp + 1], ah1, bh[2], bh[3]);
            }
        }

        // ===== epilogue 2: tanh + mix + Wo dot + quad-reduce + atomicAdd =====
#pragma unroll
        for (int s = 0; s < 2; s++) {
            float pa = 0.f, pb = 0.f;
#pragma unroll
            for (int t = 0; t < 8; t++) {
                int k0 = nh * 64 + (t >> 1) * 16 + (t & 1) * 8 + li * 2;
                float2 bpv = *(float2*)(bp_s + k0);
                float2 wov = *(float2*)(Wo_s + k0);
                pa += tanhf(D2[s][t][0] + bpv.x) * wov.x
                    + tanhf(D2[s][t][1] + bpv.y) * wov.y;
                pb += tanhf(D2[s][t][2] + bpv.x) * wov.x
                    + tanhf(D2[s][t][3] + bpv.y) * wov.y;
            }
            float va = omix * s1[s][0] + mix * pa + boe;
            float vb = omix * s1[s][1] + mix * pb + boe;
            va += __shfl_xor_sync(0xffffffffu, va, 1);
            va += __shfl_xor_sync(0xffffffffu, va, 2);
            vb += __shfl_xor_sync(0xffffffffu, vb, 1);
            vb += __shfl_xor_sync(0xffffffffu, vb, 2);
            if (li == 0) {
                int mr = mw * 32 + s * 16 + lg;
                float corr = 3.f * boe;   // boe added by all 4 quad lanes
                if (base + mr < n)
                    atomicAdd(&out[tk[mr]], wt[mr] * (va - corr));
                if (base + mr + 8 < n)
                    atomicAdd(&out[tk[mr + 8]], wt[mr + 8] * (vb - corr));
            }
        }
    }

    // reset counter for the next graph replay (all blocks read g_count at
    // start in wave 1; this write lands tens of microseconds later)
    if (j == 0 && tid == 0) g_count[e] = 0;
}

extern "C" void kernel_launch(void* const* d_in, const int* in_sizes, int n_in,
                              void* d_out, int out_size) {
    const float* feat      = (const float*)d_in[0];
    const float* Wg        = (const float*)d_in[1];
    const float* W1        = (const float*)d_in[2];
    const float* b1        = (const float*)d_in[3];
    const float* Wp        = (const float*)d_in[4];
    const float* bp        = (const float*)d_in[5];
    const float* mix_logit = (const float*)d_in[6];
    const float* Wo        = (const float*)d_in[7];
    const float* bo        = (const float*)d_in[8];
    float* out = (float*)d_out;

    cudaFuncSetAttribute(k_expert, cudaFuncAttributeMaxDynamicSharedMemorySize,
                         SMEM_BYTES);
    k_front<<<384, 256>>>(feat, Wg, W1, Wp, out);
    k_expert<<<NBv * Ev, TPB, SMEM_BYTES>>>(b1, bp, mix_logit, Wo, bo, out);
}

// round 17
// speedup vs baseline: 1.0338x; 1.0338x over previous
#include <cuda_runtime.h>
#include <cuda_fp16.h>
#include <math.h>
#include <stdint.h>

#define Bv 16384
#define Dv 256
#define Ev 8
#define GRIDB 136       // 17 blocks/expert, all co-resident (<=148 SMs, occ 1)
#define NBv 17
#define MT 256
#define TPB 512

__device__ int      g_count[Ev];     // zero at load; re-zeroed at kernel tail
__device__ unsigned g_sync;          // monotonic grid-barrier ticket counter
__device__ int   g_tok[Ev][Bv];
__device__ float g_w[Ev][Bv];
// fp16 hi images: W1 [e][quarter(4)] 16KB each (512KB), Wp [e] 32KB (256KB)
__device__ uint4 g_img4[1572864 / 16];
// fp16 image of feat: [16384 tokens][256 fp16] = 8MB
__device__ uint4 g_f16[16384 * 32];

__device__ __forceinline__ uint32_t smem_u32(const void* p) {
    uint32_t a;
    asm("{ .reg .u64 t; cvta.to.shared.u64 t, %1; cvt.u32.u64 %0, t; }"
        : "=r"(a) : "l"(p));
    return a;
}
__device__ __forceinline__ uint32_t packhf(float even, float odd) {
    uint32_t r;
    asm("cvt.rn.f16x2.f32 %0, %1, %2;" : "=r"(r) : "f"(odd), "f"(even));
    return r;
}
__device__ __forceinline__ void ldsm4(uint32_t addr, uint32_t* r) {
    asm volatile("ldmatrix.sync.aligned.m8n8.x4.shared.b16 {%0,%1,%2,%3}, [%4];"
        : "=r"(r[0]), "=r"(r[1]), "=r"(r[2]), "=r"(r[3]) : "r"(addr));
}
__device__ __forceinline__ void mma_hf(float* d, const uint32_t* a,
                                       uint32_t b0, uint32_t b1) {
    asm volatile("mma.sync.aligned.m16n8k16.row.col.f32.f16.f16.f32 "
        "{%0,%1,%2,%3}, {%4,%5,%6,%7}, {%8,%9}, {%0,%1,%2,%3};"
        : "+f"(d[0]), "+f"(d[1]), "+f"(d[2]), "+f"(d[3])
        : "r"(a[0]), "r"(a[1]), "r"(a[2]), "r"(a[3]), "r"(b0), "r"(b1));
}

// smem map (bytes) — expert phase:
//   BUF 0..65536: GEMM1: A_hi 0 (32K), W1q 32768 (16K)
//                 GEMM2: core_hi 0..65536 (256 rows x 256B)
//   Wp 65536 (32K), tk 98304 (1K), wt 99328 (1K),
//   b1 100352, bp 100864, Wo 101376 -> 101888
// gate phase reuses BUF: WgT 0 (8K), w0s 8192, w1s 8704+, e0s, e1s, cnt...
#define OFF_WH  32768
#define OFF_PH  65536
#define SMEM_BYTES 101888

__global__ void __launch_bounds__(TPB, 1) k_fused(
    const float* __restrict__ feat, const float* __restrict__ Wg,
    const float* __restrict__ W1g, const float* __restrict__ Wpg,
    const float* __restrict__ b1g, const float* __restrict__ bpg,
    const float* __restrict__ mix_logit,
    const float* __restrict__ Wog, const float* __restrict__ bog,
    float* __restrict__ out)
{
    extern __shared__ __align__(1024) char smb[];
    const int tid = threadIdx.x;
    const int bid = blockIdx.x;
    unsigned char* img = (unsigned char*)g_img4;

    // ================== PHASE A: gate (bid<128) / prep (bid>=128) ==========
    if (bid < 128) {
        float* WgT = (float*)smb;                       // 8KB
        float* w0s = (float*)(smb + 8192);              // 128 f
        float* w1s = (float*)(smb + 8704);
        int*   e0s = (int*)(smb + 9216);
        int*   e1s = (int*)(smb + 9728);
        int*   cnt   = (int*)(smb + 10240);
        int*   gbase = (int*)(smb + 10272);
        int*   cur   = (int*)(smb + 10304);

        for (int i = tid; i < Dv * Ev; i += TPB)
            WgT[(i & 7) * 256 + (i >> 3)] = Wg[i];
        if (tid < Ev) cnt[tid] = 0;
        __syncthreads();

        const int tq  = tid & 3;        // d range [tq*64, tq*64+64)
        const int tl  = tid >> 2;       // local token 0..127
        const int tok = bid * 128 + tl;
        const float* x = feat + (size_t)tok * Dv + tq * 64;
        unsigned char* f16 = (unsigned char*)g_f16;

        float acc[Ev];
#pragma unroll
        for (int e = 0; e < Ev; e++) acc[e] = 0.f;
#pragma unroll
        for (int i = 0; i < 16; i++) {
            float4 x4 = *(const float4*)(x + i * 4);
            *(uint2*)(f16 + (size_t)tok * 512 + tq * 128 + i * 8) =
                make_uint2(packhf(x4.x, x4.y), packhf(x4.z, x4.w));
#pragma unroll
            for (int e = 0; e < Ev; e++) {
                const float* wr = WgT + e * 256 + tq * 64 + i * 4;
                acc[e] += x4.x * wr[0] + x4.y * wr[1]
                        + x4.z * wr[2] + x4.w * wr[3];
            }
        }
#pragma unroll
        for (int e = 0; e < Ev; e++) {
            acc[e] += __shfl_xor_sync(0xffffffffu, acc[e], 1);
            acc[e] += __shfl_xor_sync(0xffffffffu, acc[e], 2);
        }

        if (tq == 0) {
            out[tok] = 0.f;
            float m = acc[0];
#pragma unroll
            for (int e = 1; e < Ev; e++) m = fmaxf(m, acc[e]);
            float g[Ev], sum = 0.f;
#pragma unroll
            for (int e = 0; e < Ev; e++) { g[e] = expf(acc[e] - m); sum += g[e]; }
            float inv = 1.f / sum;
#pragma unroll
            for (int e = 0; e < Ev; e++) g[e] *= inv;
            int i0 = 0;
#pragma unroll
            for (int e = 1; e < Ev; e++) if (g[e] > g[i0]) i0 = e;
            int i1 = -1;
#pragma unroll
            for (int e = 0; e < Ev; e++) {
                if (e == i0) continue;
                if (i1 < 0 || g[e] > g[i1]) i1 = e;
            }
            float denom = g[i0] + g[i1] + 1e-10f;
            e0s[tl] = i0; w0s[tl] = g[i0] / denom;
            e1s[tl] = i1; w1s[tl] = g[i1] / denom;
        }
        __syncthreads();

        if (tid < 128) {
            atomicAdd(&cnt[e0s[tid]], 1);
            atomicAdd(&cnt[e1s[tid]], 1);
        }
        __syncthreads();
        if (tid < Ev) {
            gbase[tid] = atomicAdd(&g_count[tid], cnt[tid]);
            cur[tid] = 0;
        }
        __syncthreads();
        if (tid < 128) {
            int t2 = bid * 128 + tid;
            int e0 = e0s[tid];
            int p0 = atomicAdd(&cur[e0], 1);
            g_tok[e0][gbase[e0] + p0] = t2;
            g_w[e0][gbase[e0] + p0] = w0s[tid];
            int e1 = e1s[tid];
            int p1 = atomicAdd(&cur[e1], 1);
            g_tok[e1][gbase[e1] + p1] = t2;
            g_w[e1][gbase[e1] + p1] = w1s[tid];
        }
    } else {
        // ---- prep: one expert's weight images per block (bid-128 = e) ----
        const int e = bid - 128;
        for (int i = tid; i < 16384; i += TPB) {
            int h = i >> 7, d2 = i & 127;
            int dg = d2 * 2;
            float v0 = W1g[e * 32768 + dg * 128 + h];
            float v1 = W1g[e * 32768 + (dg + 1) * 128 + h];
            int quarter = dg >> 6, dl = dg & 63;
            uint32_t off = (uint32_t)h * 128
                         + (((uint32_t)dl * 2) ^ ((h & 7) * 16));
            *(uint32_t*)(img + (uint32_t)(e * 4 + quarter) * 16384u + off)
                = packhf(v0, v1);
        }
        for (int i = tid; i < 8192; i += TPB) {
            int k = i >> 6, h2 = i & 63;
            int hg = h2 * 2;
            float v0 = Wpg[e * 16384 + hg * 128 + k];
            float v1 = Wpg[e * 16384 + (hg + 1) * 128 + k];
            uint32_t off = (uint32_t)k * 256
                         + (((uint32_t)hg * 2) ^ ((k & 7) * 16));
            *(uint32_t*)(img + 524288u + (uint32_t)e * 32768u + off)
                = packhf(v0, v1);
        }
    }

    // ================== GRID BARRIER (monotonic ticket) ==================
    {
        __shared__ unsigned tgt;
        __threadfence();               // release all phase-A writes
        __syncthreads();
        if (tid == 0) {
            unsigned t = atomicAdd(&g_sync, 1u);
            tgt = (t / GRIDB + 1u) * GRIDB;
            while (*(volatile unsigned*)&g_sync < tgt) { }
        }
        __syncthreads();
        __threadfence();               // acquire
    }

    // ================== PHASE B: expert compute ==================
    int*   tk   = (int*)(smb + 98304);
    float* wt   = (float*)(smb + 99328);
    float* b1_s = (float*)(smb + 100352);
    float* bp_s = (float*)(smb + 100864);
    float* Wo_s = (float*)(smb + 101376);

    const int e    = bid & 7;
    const int j    = bid >> 3;
    const int warp = tid >> 5;
    const int lane = tid & 31;
    const int mw   = warp & 7;
    const int nh   = warp >> 3;
    const int li   = lane & 3;
    const int lg   = lane >> 2;
    const uint32_t sb = smem_u32(smb);
    const unsigned char* f16 = (const unsigned char*)g_f16;

    __syncthreads();                   // phase-A smem reuse
    {
        const uint4* s = g_img4 + 32768 + (size_t)e * 2048;
        uint4* d = (uint4*)(smb + OFF_PH);
        for (int u = tid; u < 2048; u += TPB) d[u] = s[u];
    }
    if (tid < 128) {
        b1_s[tid] = b1g[e * 128 + tid];
        bp_s[tid] = bpg[e * 128 + tid];
        Wo_s[tid] = Wog[e * 128 + tid];
    }
    const float mix  = 1.f / (1.f + expf(-mix_logit[e]));
    const float omix = 1.f - mix;
    const float boe  = (nh == 0) ? bog[e] : 0.f;
    const int   n    = g_count[e];

    const int matA = lane >> 3;
    const uint32_t a_koff = (uint32_t)(matA >> 1) * 16;
    const uint32_t sw     = (uint32_t)(lane & 7) * 16;
    const uint32_t arow0  = (uint32_t)(mw * 32 + (matA & 1) * 8 + (lane & 7));
    const int jt = matA >> 1, kc = matA & 1;
    const uint32_t brow0  = (uint32_t)(nh * 64 + jt * 8 + (lane & 7));
    const uint32_t b_koff = (uint32_t)kc * 16;

    for (int tile = j; tile * MT < n; tile += NBv) {
        const int base = tile * MT;
        __syncthreads();
        if (tid < 256) {
            int idx = min(base + tid, n - 1);
            tk[tid] = g_tok[e][idx];
            wt[tid] = g_w[e][idx];
        }

        float D1[2][8][4];
#pragma unroll
        for (int s = 0; s < 2; s++)
#pragma unroll
            for (int t = 0; t < 8; t++)
#pragma unroll
                for (int q = 0; q < 4; q++) D1[s][t][q] = 0.f;

        for (int q = 0; q < 4; q++) {
            __syncthreads();
            for (int u = tid; u < 2048; u += TPB) {
                int ts = u >> 3, c = u & 7;
                uint4 v = *(const uint4*)(f16 + (size_t)tk[ts] * 512
                                          + q * 128 + c * 16);
                uint32_t off = (uint32_t)ts * 128
                             + (((uint32_t)c * 16) ^ ((ts & 7) * 16));
                *(uint4*)(smb + off) = v;
            }
            {
                const uint4* s = g_img4 + (size_t)(e * 4 + q) * 1024;
                uint4* d = (uint4*)(smb + OFF_WH);
                for (int u = tid; u < 1024; u += TPB) d[u] = s[u];
            }
            __syncthreads();

            for (int ks = 0; ks < 4; ks++) {
                uint32_t kx  = (uint32_t)ks * 32;
                uint32_t akx = (kx + a_koff) ^ sw;
                uint32_t ah0[4], ah1[4];
                ldsm4(sb + arow0 * 128 + akx, ah0);
                ldsm4(sb + (arow0 + 16) * 128 + akx, ah1);
#pragma unroll
                for (int ntp = 0; ntp < 4; ntp++) {
                    uint32_t bkx = ((kx + b_koff) ^ sw)
                                 + (brow0 + ntp * 16) * 128;
                    uint32_t bh[4];
                    ldsm4(sb + OFF_WH + bkx, bh);
                    mma_hf(D1[0][2 * ntp],     ah0, bh[0], bh[1]);
                    mma_hf(D1[0][2 * ntp + 1], ah0, bh[2], bh[3]);
                    mma_hf(D1[1][2 * ntp],     ah1, bh[0], bh[1]);
                    mma_hf(D1[1][2 * ntp + 1], ah1, bh[2], bh[3]);
                }
            }
        }

        __syncthreads();
        float s1[2][2];
#pragma unroll
        for (int s = 0; s < 2; s++) {
            const int tok0 = mw * 32 + s * 16 + lg;
            const uint32_t sw0 = (uint32_t)(tok0 & 7) * 16;
            const uint32_t sw1 = (uint32_t)((tok0 + 8) & 7) * 16;
            float a = 0.f, b = 0.f;
#pragma unroll
            for (int t = 0; t < 8; t++) {
                int h0 = nh * 64 + (t >> 1) * 16 + (t & 1) * 8 + li * 2;
                float2 b1v = *(float2*)(b1_s + h0);
                float2 wov = *(float2*)(Wo_s + h0);
                float c0 = fmaxf(D1[s][t][0] + b1v.x, 0.f);
                float c1 = fmaxf(D1[s][t][1] + b1v.y, 0.f);
                float c2 = fmaxf(D1[s][t][2] + b1v.x, 0.f);
                float c3 = fmaxf(D1[s][t][3] + b1v.y, 0.f);
                a += c0 * wov.x + c1 * wov.y;
                b += c2 * wov.x + c3 * wov.y;
                uint32_t col = (uint32_t)h0 * 2;
                uint32_t o0 = (uint32_t)tok0 * 256 + (col ^ sw0);
                uint32_t o1 = (uint32_t)(tok0 + 8) * 256 + (col ^ sw1);
                *(uint32_t*)(smb + o0) = packhf(c0, c1);
                *(uint32_t*)(smb + o1) = packhf(c2, c3);
            }
            s1[s][0] = a; s1[s][1] = b;
        }
        __syncthreads();

        float D2[2][8][4];
#pragma unroll
        for (int s = 0; s < 2; s++)
#pragma unroll
            for (int t = 0; t < 8; t++)
#pragma unroll
                for (int q = 0; q < 4; q++) D2[s][t][q] = 0.f;
        for (int ks = 0; ks < 8; ks++) {
            uint32_t kx  = (uint32_t)ks * 32;
            uint32_t akx = (kx + a_koff) ^ sw;
            uint32_t ah0[4], ah1[4];
            ldsm4(sb + arow0 * 256 + akx, ah0);
            ldsm4(sb + (arow0 + 16) * 256 + akx, ah1);
#pragma unroll
            for (int ntp = 0; ntp < 4; ntp++) {
                uint32_t bkx = ((kx + b_koff) ^ sw) + (brow0 + ntp * 16) * 256;
                uint32_t bh[4];
                ldsm4(sb + OFF_PH + bkx, bh);
                mma_hf(D2[0][2 * ntp],     ah0, bh[0], bh[1]);
                mma_hf(D2[0][2 * ntp + 1], ah0, bh[2], bh[3]);
                mma_hf(D2[1][2 * ntp],     ah1, bh[0], bh[1]);
                mma_hf(D2[1][2 * ntp + 1], ah1, bh[2], bh[3]);
            }
        }

#pragma unroll
        for (int s = 0; s < 2; s++) {
            float pa = 0.f, pb = 0.f;
#pragma unroll
            for (int t = 0; t < 8; t++) {
                int k0 = nh * 64 + (t >> 1) * 16 + (t & 1) * 8 + li * 2;
                float2 bpv = *(float2*)(bp_s + k0);
                float2 wov = *(float2*)(Wo_s + k0);
                pa += tanhf(D2[s][t][0] + bpv.x) * wov.x
                    + tanhf(D2[s][t][1] + bpv.y) * wov.y;
                pb += tanhf(D2[s][t][2] + bpv.x) * wov.x
                    + tanhf(D2[s][t][3] + bpv.y) * wov.y;
            }
            float va = omix * s1[s][0] + mix * pa + boe;
            float vb = omix * s1[s][1] + mix * pb + boe;
            va += __shfl_xor_sync(0xffffffffu, va, 1);
            va += __shfl_xor_sync(0xffffffffu, va, 2);
            vb += __shfl_xor_sync(0xffffffffu, vb, 1);
            vb += __shfl_xor_sync(0xffffffffu, vb, 2);
            if (li == 0) {
                int mr = mw * 32 + s * 16 + lg;
                float corr = 3.f * boe;
                if (base + mr < n)
                    atomicAdd(&out[tk[mr]], wt[mr] * (va - corr));
                if (base + mr + 8 < n)
                    atomicAdd(&out[tk[mr + 8]], wt[mr + 8] * (vb - corr));
            }
        }
    }

    // reset counters for next replay (all blocks read g_count right after
    // the grid barrier; this write lands much later)
    if (j == 0 && tid == 0) g_count[e] = 0;
}

extern "C" void kernel_launch(void* const* d_in, const int* in_sizes, int n_in,
                              void* d_out, int out_size) {
    const float* feat      = (const float*)d_in[0];
    const float* Wg        = (const float*)d_in[1];
    const float* W1        = (const float*)d_in[2];
    const float* b1        = (const float*)d_in[3];
    const float* Wp        = (const float*)d_in[4];
    const float* bp        = (const float*)d_in[5];
    const float* mix_logit = (const float*)d_in[6];
    const float* Wo        = (const float*)d_in[7];
    const float* bo        = (const float*)d_in[8];
    float* out = (float*)d_out;

    cudaFuncSetAttribute(k_fused, cudaFuncAttributeMaxDynamicSharedMemorySize,
                         SMEM_BYTES);
    k_fused<<<GRIDB, TPB, SMEM_BYTES>>>(feat, Wg, W1, Wp, b1, bp, mix_logit,
                                        Wo, bo, out);
}